// round 12
// baseline (speedup 1.0000x reference)
#include <cuda_runtime.h>
#include <cuda_fp16.h>
#include <cstdint>
#include <math.h>

#define B_ 4
#define S_ 4096
#define D_ 256
#define BS_ (B_ * S_)

#define TILE_M 128
#define TILE_N 256
#define TILE_K 64

// ---------------- scratch (__device__ globals; no allocs) ----------------
__device__ __half g_q_hi[BS_ * D_];
__device__ __half g_k_hi[BS_ * D_];
__device__ __half g_v_hi[BS_ * D_];
__device__ __half g_qp_h[BS_ * D_];
__device__ __half g_kp_hi[BS_ * D_], g_kp_lo[BS_ * D_];
__device__ __half g_vpT_hi[BS_ * D_], g_vpT_lo[BS_ * D_];
__device__ __half g_ctx_hi[BS_ * D_];
__device__ __half g_WT_hi[4][D_ * D_], g_WT_lo[4][D_ * D_];
__device__ __half g_attn_h[(size_t)B_ * S_ * S_];
__device__ float  g_pv_part[4][BS_ * D_];
__device__ float  g_attn_f[(size_t)B_ * S_ * S_];   // fallback
__device__ float  g_z[BS_ * D_];                    // fallback

// ---------------- helpers ----------------
__device__ __forceinline__ uint32_t smem_u32(const void* p) {
    uint32_t a;
    asm("{ .reg .u64 t; cvta.to.shared.u64 t, %1; cvt.u32.u64 %0, t; }" : "=r"(a) : "l"(p));
    return a;
}
#define SWZ128(o) ((o) ^ (((o) >> 3) & 0x70))

__device__ __forceinline__ void cpa16(uint32_t s, const void* g) {
    asm volatile("cp.async.cg.shared.global [%0], [%1], 16;" :: "r"(s), "l"(g));
}
#define CP_COMMIT() asm volatile("cp.async.commit_group;")
#define CP_WAIT1()  asm volatile("cp.async.wait_group 1;" ::: "memory")
#define CP_WAIT0()  asm volatile("cp.async.wait_group 0;" ::: "memory")

__device__ __forceinline__ void ldm_x4(uint32_t* r, uint32_t addr) {
    asm volatile("ldmatrix.sync.aligned.m8n8.x4.shared.b16 {%0,%1,%2,%3}, [%4];"
                 : "=r"(r[0]), "=r"(r[1]), "=r"(r[2]), "=r"(r[3]) : "r"(addr));
}
__device__ __forceinline__ void mma16816(float* c, const uint32_t* a, const uint32_t* b) {
    asm volatile("mma.sync.aligned.m16n8k16.row.col.f32.f16.f16.f32 "
                 "{%0,%1,%2,%3}, {%4,%5,%6,%7}, {%8,%9}, {%0,%1,%2,%3};"
                 : "+f"(c[0]), "+f"(c[1]), "+f"(c[2]), "+f"(c[3])
                 : "r"(a[0]), "r"(a[1]), "r"(a[2]), "r"(a[3]), "r"(b[0]), "r"(b[1]));
}

__device__ __forceinline__ uint32_t pack_h2(float a, float b) {
    __half2 h = __floats2half2_rn(a, b);
    return *reinterpret_cast<uint32_t*>(&h);
}
__device__ __forceinline__ void residual2(uint32_t h, float a, float b, float& ra, float& rb) {
    __half2 hh = *reinterpret_cast<__half2*>(&h);
    ra = a - __low2float(hh);
    rb = b - __high2float(hh);
}

// ----------------------------------------------------------------------------
// mma.sync fp16 2-term GEMM: C = alpha * A @ B^T (+bias) (+causal)
// CTA tile 128x256x64; 16 warps, warp tile 64x32; 2-stage pipeline.
// MMA issue order: all-hi (16 independent accs) then all-lo — hides the
// per-accumulator RAW latency while keeping per-acc op order (bit-identical).
// cmode: 0 plain, 1 logits, 2 PV split-K, 3 fused q/k/v projections
// ----------------------------------------------------------------------------
#define OFF_A  0
#define OFF_BH 16384
#define OFF_BL 49152
#define STAGE_B 81920
#define SMEM_GEMM (2 * STAGE_B)

__device__ __forceinline__ void tile_cp(uint32_t sbase, const __half* g,
                                        size_t ldK, int nrows, int tid) {
    const int total = nrows * 8;
    for (int u = tid; u < total; u += 512) {
        int r = u >> 3, c = u & 7;
        uint32_t off = (uint32_t)(r * 128 + c * 16);
        cpa16(sbase + SWZ128(off), (const char*)(g + (size_t)r * ldK) + (c << 4));
    }
}

__global__ __launch_bounds__(512, 1)
void gemm_mma(const __half* __restrict__ Ain, const __half* __restrict__ Bhin,
              const __half* __restrict__ Blin,
              int N, int K, size_t sA, size_t sB, size_t sC,
              float alpha, const float* __restrict__ bias,
              const float* __restrict__ bias2, const float* __restrict__ bias3,
              int cmode,
              float* __restrict__ Cf, __half* __restrict__ Ch,
              __half* __restrict__ Chi, __half* __restrict__ Clo)
{
    const int tid = threadIdx.x;
    const int z = blockIdx.z;
    const int n0 = blockIdx.x * TILE_N;
    int m0, slice = 0;
    if (cmode == 2) {
        const int g = blockIdx.y;
        const int mt = (int)(gridDim.y >> 2) - 1 - (g >> 2);   // heavy first
        slice = g & 3;
        m0 = mt * TILE_M;
    } else {
        m0 = blockIdx.y * TILE_M;
    }
    if (cmode == 1 && n0 > m0) return;          // fully-masked logits tile

    // operand / output selection
    const __half *Ah, *Bh, *Bl;
    const float* bs = bias;
    float* oF = nullptr; __half* oH = nullptr;
    __half *oHi = nullptr, *oLo = nullptr;
    __half *oTh = nullptr, *oTl = nullptr;      // transposed hi/lo (V proj)
    if (cmode == 3) {
        if (z == 0)      { Ah = g_q_hi; Bh = g_WT_hi[0]; Bl = g_WT_lo[0]; bs = bias;  oH = g_qp_h; }
        else if (z == 1) { Ah = g_k_hi; Bh = g_WT_hi[1]; Bl = g_WT_lo[1]; bs = bias2; oHi = g_kp_hi; oLo = g_kp_lo; }
        else             { Ah = g_v_hi; Bh = g_WT_hi[2]; Bl = g_WT_lo[2]; bs = bias3; oTh = g_vpT_hi; oTl = g_vpT_lo; }
    } else {
        Ah = Ain + (size_t)z * sA;
        Bh = Bhin + (size_t)z * sB;
        Bl = Blin + (size_t)z * sB;
        if (Cf)  oF = Cf + ((cmode == 2) ? ((size_t)slice * B_ + z) * sC : (size_t)z * sC);
        if (Ch)  oH = Ch + (size_t)z * sC;
        if (Chi) { oHi = Chi + (size_t)z * sC; oLo = Clo + (size_t)z * sC; }
    }

    // chunk range
    const int NCfull = K / TILE_K;
    int c0 = 0, c1 = NCfull;
    if (cmode == 2) {
        int NCm = (m0 >> 6) + 2;
        if (NCm > NCfull) NCm = NCfull;
        c0 = (slice * NCm) >> 2;
        c1 = ((slice + 1) * NCm) >> 2;
        if (c0 >= c1) {                         // empty slice: zero partial
            const float4 z4 = {0.f, 0.f, 0.f, 0.f};
#pragma unroll
            for (int it = 0; it < 16; it++) {
                int u = tid + (it << 9);
                int r = u >> 6;
                int c4 = (u & 63) << 2;
                *(float4*)(oF + (size_t)(m0 + r) * N + n0 + c4) = z4;
            }
            return;
        }
    }

    extern __shared__ char dsm[];
    const uint32_t sb = smem_u32(dsm);
    const int wid = tid >> 5;
    const int lane = tid & 31;
    const int mrow0 = (wid & 1) * 64;           // 2 warp-rows of 64
    const int ncol0 = (wid >> 1) * 32;          // 8 warp-cols of 32

    const __half* aT = Ah + (size_t)m0 * K;
    const __half* bT = Bh + (size_t)n0 * K;
    const __half* bTl = Bl + (size_t)n0 * K;

    float acc[4][4][4];
#pragma unroll
    for (int i = 0; i < 4; i++)
#pragma unroll
        for (int j = 0; j < 4; j++)
#pragma unroll
            for (int l = 0; l < 4; l++) acc[i][j][l] = 0.f;

    // prologue: prefetch chunk c0
    {
        const size_t ko = (size_t)c0 * TILE_K;
        tile_cp(sb + OFF_A, aT + ko, K, 128, tid);
        tile_cp(sb + OFF_BH, bT + ko, K, 256, tid);
        tile_cp(sb + OFF_BL, bTl + ko, K, 256, tid);
        CP_COMMIT();
    }

    const uint32_t lane15 = (uint32_t)(lane & 15);
    const uint32_t khalf = (uint32_t)((lane >> 4) << 4);

    for (int c = c0; c < c1; c++) {
        if (c + 1 < c1) {
            const uint32_t st = sb + (uint32_t)(((c + 1 - c0) & 1) * STAGE_B);
            const size_t ko = (size_t)(c + 1) * TILE_K;
            tile_cp(st + OFF_A, aT + ko, K, 128, tid);
            tile_cp(st + OFF_BH, bT + ko, K, 256, tid);
            tile_cp(st + OFF_BL, bTl + ko, K, 256, tid);
            CP_COMMIT();
            CP_WAIT1();
        } else {
            CP_WAIT0();
        }
        __syncthreads();

        const uint32_t st = sb + (uint32_t)(((c - c0) & 1) * STAGE_B);
        const uint32_t sA = st + OFF_A, sBh = st + OFF_BH, sBl = st + OFF_BL;

#pragma unroll
        for (int ks = 0; ks < 4; ks++) {
            const uint32_t kb = (uint32_t)(ks * 32) + khalf;
            uint32_t a[4][4], bh[4][2], bl[4][2];
#pragma unroll
            for (int mt = 0; mt < 4; mt++) {
                const uint32_t ro = (uint32_t)(mrow0 + mt * 16) + lane15;
                ldm_x4(a[mt], sA + SWZ128(ro * 128 + kb));
            }
#pragma unroll
            for (int g = 0; g < 2; g++) {
                const uint32_t ro = (uint32_t)(ncol0 + g * 16) + lane15;
                uint32_t th[4], tl[4];
                ldm_x4(th, sBh + SWZ128(ro * 128 + kb));
                ldm_x4(tl, sBl + SWZ128(ro * 128 + kb));
                bh[g * 2][0] = th[0]; bh[g * 2][1] = th[2];
                bh[g * 2 + 1][0] = th[1]; bh[g * 2 + 1][1] = th[3];
                bl[g * 2][0] = tl[0]; bl[g * 2][1] = tl[2];
                bl[g * 2 + 1][0] = tl[1]; bl[g * 2 + 1][1] = tl[3];
            }
            // all hi MMAs first (16 independent accumulators) ...
#pragma unroll
            for (int mt = 0; mt < 4; mt++)
#pragma unroll
                for (int nt = 0; nt < 4; nt++)
                    mma16816(acc[mt][nt], a[mt], bh[nt]);
            // ... then all lo MMAs (each 16 issues after its hi)
#pragma unroll
            for (int mt = 0; mt < 4; mt++)
#pragma unroll
                for (int nt = 0; nt < 4; nt++)
                    mma16816(acc[mt][nt], a[mt], bl[nt]);
        }
        if (c + 1 < c1) __syncthreads();
    }
    __syncthreads();

    // ---- epilogue: regs -> smem stage -> gmem ----
    float* stg = (float*)dsm;
    const int ELD = 260;
    const int rr = lane >> 2;
    const int cc = (lane & 3) * 2;
#pragma unroll
    for (int mt = 0; mt < 4; mt++)
#pragma unroll
        for (int nt = 0; nt < 4; nt++) {
            const int r = mrow0 + mt * 16 + rr;
            const int cn = ncol0 + nt * 8 + cc;
            stg[r * ELD + cn]           = acc[mt][nt][0];
            stg[r * ELD + cn + 1]       = acc[mt][nt][1];
            stg[(r + 8) * ELD + cn]     = acc[mt][nt][2];
            stg[(r + 8) * ELD + cn + 1] = acc[mt][nt][3];
        }
    __syncthreads();

    if (oTh) {
        // transposed hi/lo write: vpT[b][n][s], tile m0 within batch b
        const int b = m0 >> 12;
        const int s0 = m0 & (S_ - 1);
#pragma unroll 1
        for (int it = 0; it < 16; it++) {
            const int u = tid + (it << 9);       // 0..8191
            const int n = u >> 5;                // 0..255
            const int mq = (u & 31) << 2;        // 0..124
            const float bv = bs[n];
            float v0 = stg[(mq + 0) * ELD + n] + bv;
            float v1 = stg[(mq + 1) * ELD + n] + bv;
            float v2 = stg[(mq + 2) * ELD + n] + bv;
            float v3 = stg[(mq + 3) * ELD + n] + bv;
            uint32_t h0 = pack_h2(v0, v1), h1 = pack_h2(v2, v3);
            float r0, r1, r2, r3;
            residual2(h0, v0, v1, r0, r1);
            residual2(h1, v2, v3, r2, r3);
            const size_t o = ((size_t)b * D_ + n) * S_ + s0 + mq;
            uint2 hv = {h0, h1};
            uint2 lv = {pack_h2(r0, r1), pack_h2(r2, r3)};
            *(uint2*)(oTh + o) = hv;
            *(uint2*)(oTl + o) = lv;
        }
        return;
    }

#pragma unroll 1
    for (int it = 0; it < 16; it++) {
        const int u = tid + (it << 9);
        const int r = u >> 6;
        const int f = (u & 63) << 2;
        const float* s = stg + r * ELD + f;
        float v0 = s[0] * alpha, v1 = s[1] * alpha, v2 = s[2] * alpha, v3 = s[3] * alpha;
        const int n = n0 + f;
        const int mi = m0 + r;
        const size_t m = (size_t)mi;
        if (bs) {
            float4 bv = *(const float4*)(bs + n);
            v0 += bv.x; v1 += bv.y; v2 += bv.z; v3 += bv.w;
        }
        if (cmode == 1) {
            if (n + 0 > mi) v0 += -1e9f;
            if (n + 1 > mi) v1 += -1e9f;
            if (n + 2 > mi) v2 += -1e9f;
            if (n + 3 > mi) v3 += -1e9f;
        }
        const size_t o = m * (size_t)N + n;
        if (oF) {
            float4 ov = {v0, v1, v2, v3};
            *(float4*)(oF + o) = ov;
        }
        if (oH) {
            uint2 hv = {pack_h2(v0, v1), pack_h2(v2, v3)};
            *(uint2*)(oH + o) = hv;
        }
        if (oHi) {
            uint32_t h0 = pack_h2(v0, v1), h1 = pack_h2(v2, v3);
            float r0, r1, r2, r3;
            residual2(h0, v0, v1, r0, r1);
            residual2(h1, v2, v3, r2, r3);
            uint2 hv = {h0, h1};
            uint2 lv = {pack_h2(r0, r1), pack_h2(r2, r3)};
            *(uint2*)(oHi + o) = hv;
            *(uint2*)(oLo + o) = lv;
        }
    }
}

// ---------------- fused input -> fp16 hi (z picks q/k/v) ----------------
__global__ __launch_bounds__(256)
void convert_hi3(const float* __restrict__ q, const float* __restrict__ k,
                 const float* __restrict__ v, int n4)
{
    int i = blockIdx.x * blockDim.x + threadIdx.x;
    if (i >= n4) return;
    const float* in;
    __half* hi;
    if (blockIdx.z == 0)      { in = q; hi = g_q_hi; }
    else if (blockIdx.z == 1) { in = k; hi = g_k_hi; }
    else                      { in = v; hi = g_v_hi; }
    float4 vv = ((const float4*)in)[i];
    uint2 hv = {pack_h2(vv.x, vv.y), pack_h2(vv.z, vv.w)};
    ((uint2*)hi)[i] = hv;
}

// ---------------- fused weight transpose+split (z picks Wq/Wk/Wv/Wo) ----------------
__global__ __launch_bounds__(256)
void transpose_W(const float* __restrict__ Wq, const float* __restrict__ Wk,
                 const float* __restrict__ Wv, const float* __restrict__ Wo)
{
    __shared__ float t[32][33];
    const int z = blockIdx.z;
    const float* in = (z == 0) ? Wq : (z == 1) ? Wk : (z == 2) ? Wv : Wo;
    __half* ohi = &g_WT_hi[z][0];
    __half* olo = &g_WT_lo[z][0];
    const int r0 = blockIdx.y * 32, c0 = blockIdx.x * 32;
    const int tx = threadIdx.x, ty = threadIdx.y;
#pragma unroll
    for (int j = 0; j < 32; j += 8)
        t[ty + j][tx] = in[(size_t)(r0 + ty + j) * D_ + c0 + tx];
    __syncthreads();
#pragma unroll
    for (int j = 0; j < 32; j += 8) {
        float v = t[tx][ty + j];
        __half h = __float2half_rn(v);
        __half l = __float2half_rn(v - __half2float(h));
        size_t o = (size_t)(c0 + ty + j) * D_ + r0 + tx;
        ohi[o] = h; olo[o] = l;
    }
}

// ---------------- PV split-K reduce: ctx hi = sum of 4 partials ----------------
__global__ __launch_bounds__(256)
void reduce_ctx(int n4)
{
    int i = blockIdx.x * blockDim.x + threadIdx.x;
    if (i >= n4) return;
    const size_t stride = (size_t)BS_ * D_ / 4;
    const float4* p = (const float4*)&g_pv_part[0][0];
    float4 a = p[i], b = p[i + stride], c = p[i + 2 * stride], d = p[i + 3 * stride];
    float v0 = a.x + b.x + c.x + d.x;
    float v1 = a.y + b.y + c.y + d.y;
    float v2 = a.z + b.z + c.z + d.z;
    float v3 = a.w + b.w + c.w + d.w;
    uint2 hv = {pack_h2(v0, v1), pack_h2(v2, v3)};
    ((uint2*)g_ctx_hi)[i] = hv;
}

// ---------------- causal softmax: 256 threads ----------------
__global__ __launch_bounds__(256)
void softmax_kernel(float* __restrict__ attn, __half* __restrict__ ah)
{
    __shared__ float buf[S_];
    __shared__ float red[8];
    __shared__ float s_max, s_sum;

    const size_t rb = (size_t)blockIdx.x * S_;
    float* row = attn + rb;
    const int t = threadIdx.x;
    const int m = blockIdx.x & (S_ - 1);
    const int L = m + 1;
    const int L4 = (L + 3) & ~3;
    const int Lpad = ((m >> 7) + 1) << 7;
    const float NINF = __int_as_float(0xff800000);

    float mx = -1e30f;
    for (int i = t * 4; i < L4; i += 1024) {
        float4 v = *(const float4*)(row + i);
        if (i + 0 >= L) v.x = NINF;
        if (i + 1 >= L) v.y = NINF;
        if (i + 2 >= L) v.z = NINF;
        if (i + 3 >= L) v.w = NINF;
        *(float4*)(buf + i) = v;
        mx = fmaxf(mx, fmaxf(fmaxf(v.x, v.y), fmaxf(v.z, v.w)));
    }
#pragma unroll
    for (int o = 16; o; o >>= 1) mx = fmaxf(mx, __shfl_xor_sync(0xffffffffu, mx, o));
    if ((t & 31) == 0) red[t >> 5] = mx;
    __syncthreads();
    if (t == 0) {
        float v = red[0];
#pragma unroll
        for (int i = 1; i < 8; i++) v = fmaxf(v, red[i]);
        s_max = v;
    }
    __syncthreads();
    const float mxv = s_max;

    float sum = 0.f;
    for (int i = t * 4; i < L4; i += 1024) {
        float4 v = *(const float4*)(buf + i);
        v.x = __expf(v.x - mxv); v.y = __expf(v.y - mxv);
        v.z = __expf(v.z - mxv); v.w = __expf(v.w - mxv);
        *(float4*)(buf + i) = v;
        sum += v.x + v.y + v.z + v.w;
    }
#pragma unroll
    for (int o = 16; o; o >>= 1) sum += __shfl_xor_sync(0xffffffffu, sum, o);
    if ((t & 31) == 0) red[t >> 5] = sum;
    __syncthreads();
    if (t == 0) {
        float v = red[0];
#pragma unroll
        for (int i = 1; i < 8; i++) v += red[i];
        s_sum = v;
    }
    __syncthreads();
    const float inv = 1.f / s_sum;

    for (int i = t * 4; i < L4; i += 1024) {
        float4 v = *(const float4*)(buf + i);
        v.x *= inv; v.y *= inv; v.z *= inv; v.w *= inv;
        *(float4*)(row + i) = v;
        uint2 hv = {pack_h2(v.x, v.y), pack_h2(v.z, v.w)};
        *(uint2*)(ah + rb + i) = hv;
    }
    const uint2 z2 = {0u, 0u};
    const float4 z4 = {0.f, 0.f, 0.f, 0.f};
    for (int i = L4 + t * 4; i < S_; i += 1024) {
        *(float4*)(row + i) = z4;
        if (i < Lpad) *(uint2*)(ah + rb + i) = z2;
    }
}

// ---------------- launch ----------------
extern "C" void kernel_launch(void* const* d_in, const int* in_sizes, int n_in,
                              void* d_out, int out_size)
{
    const float* q    = (const float*)d_in[0];
    const float* k    = (const float*)d_in[1];
    const float* v    = (const float*)d_in[2];
    const float* Wq   = (const float*)d_in[4];
    const float* bq   = (const float*)d_in[5];
    const float* Wk   = (const float*)d_in[6];
    const float* bk   = (const float*)d_in[7];
    const float* Wv   = (const float*)d_in[8];
    const float* bv   = (const float*)d_in[9];
    const float* Wo   = (const float*)d_in[10];
    const float* bo   = (const float*)d_in[11];

#define SYM(p, s) cudaGetSymbolAddress((void**)&p, s)
    __half *qph, *kph, *kpl, *vpTh, *vpTl, *ctxh, *ath;
    __half *WTh, *WTl;
    float *pvp, *attn_scr, *z_scr;
    SYM(qph, g_qp_h);
    SYM(kph, g_kp_hi); SYM(kpl, g_kp_lo);
    SYM(vpTh, g_vpT_hi); SYM(vpTl, g_vpT_lo);
    SYM(ctxh, g_ctx_hi);
    SYM(ath, g_attn_h);
    SYM(WTh, (g_WT_hi[0][0]));   SYM(WTl, (g_WT_lo[0][0]));
    SYM(pvp, (g_pv_part[0][0]));
    SYM(attn_scr, g_attn_f); SYM(z_scr, g_z);

    const size_t zN = (size_t)BS_ * D_;
    const size_t aN = (size_t)B_ * S_ * S_;
    float* out = (float*)d_out;
    float *z_out, *attn_out;
    if ((size_t)out_size >= zN + aN) { z_out = out; attn_out = out + zN; }
    else if ((size_t)out_size == aN) { attn_out = out; z_out = z_scr; }
    else                             { z_out = out; attn_out = attn_scr; }

    cudaFuncSetAttribute(gemm_mma, cudaFuncAttributeMaxDynamicSharedMemorySize, SMEM_GEMM);

    const int n4 = BS_ * D_ / 4;
    dim3 tb(32, 8);

    // 0) inputs -> fp16 hi (fused q,k,v)
    dim3 gcv((n4 + 255) / 256, 1, 3);
    convert_hi3<<<gcv, 256>>>(q, k, v, n4);

    // 1) transpose+split all weights
    dim3 tgw(D_ / 32, D_ / 32, 4);
    transpose_W<<<tgw, tb>>>(Wq, Wk, Wv, Wo);

    // 2) fused projections (cmode 3); V writes vpT hi/lo transposed
    dim3 gproj3(D_ / TILE_N, BS_ / TILE_M, 3);
    gemm_mma<<<gproj3, 512, SMEM_GEMM>>>(nullptr, nullptr, nullptr,
        D_, D_, 0, 0, 0, 1.f, bq, bk, bv, 3, nullptr, nullptr, nullptr, nullptr);

    // 3) logits = qp @ kp^T / 16 + causal (cmode 1)
    dim3 glog(S_ / TILE_N, S_ / TILE_M, B_);
    gemm_mma<<<glog, 512, SMEM_GEMM>>>(qph, kph, kpl,
        S_, D_, (size_t)S_ * D_, (size_t)S_ * D_, (size_t)S_ * S_,
        1.f / 16.f, nullptr, nullptr, nullptr, 1, attn_out, nullptr, nullptr, nullptr);

    // 4) causal softmax (+ fp16 emit)
    softmax_kernel<<<B_ * S_, 256>>>(attn_out, ath);

    // 5) PV split-K (cmode 2; fp32 partials)
    dim3 gpv(D_ / TILE_N, (S_ / TILE_M) * 4, B_);
    gemm_mma<<<gpv, 512, SMEM_GEMM>>>(ath, vpTh, vpTl,
        D_, S_, (size_t)S_ * S_, (size_t)D_ * S_, (size_t)S_ * D_,
        1.f, nullptr, nullptr, nullptr, 2, pvp, nullptr, nullptr, nullptr);

    // 6) reduce partials -> ctx hi
    reduce_ctx<<<(n4 + 255) / 256, 256>>>(n4);

    // 7) z = ctx @ Wo + bo (cmode 0)
    gemm_mma<<<dim3(D_ / TILE_N, BS_ / TILE_M, 1), 512, SMEM_GEMM>>>(ctxh,
        WTh + 3 * D_ * D_, WTl + 3 * D_ * D_,
        D_, D_, 0, 0, 0, 1.f, bo, nullptr, nullptr, 0, z_out, nullptr, nullptr, nullptr);
}

// round 13
// speedup vs baseline: 1.0965x; 1.0965x over previous
#include <cuda_runtime.h>
#include <cuda_fp16.h>
#include <cstdint>
#include <math.h>

#define B_ 4
#define S_ 4096
#define D_ 256
#define BS_ (B_ * S_)

#define TILE_M 128
#define TILE_N 128
#define TILE_K 64

// ---------------- scratch (__device__ globals; no allocs) ----------------
__device__ __half g_q_hi[BS_ * D_];
__device__ __half g_k_hi[BS_ * D_];
__device__ __half g_v_hi[BS_ * D_];
__device__ __half g_qp_h[BS_ * D_];
__device__ __half g_kp_hi[BS_ * D_], g_kp_lo[BS_ * D_];
__device__ __half g_vpT_hi[BS_ * D_], g_vpT_lo[BS_ * D_];
__device__ __half g_ctx_hi[BS_ * D_];
__device__ __half g_WT_hi[4][D_ * D_], g_WT_lo[4][D_ * D_];
__device__ __half g_attn_h[(size_t)B_ * S_ * S_];
__device__ float  g_pv_part[4][BS_ * D_];
__device__ float  g_attn_f[(size_t)B_ * S_ * S_];   // fallback
__device__ float  g_z[BS_ * D_];                    // fallback

// ---------------- helpers ----------------
__device__ __forceinline__ uint32_t smem_u32(const void* p) {
    uint32_t a;
    asm("{ .reg .u64 t; cvta.to.shared.u64 t, %1; cvt.u32.u64 %0, t; }" : "=r"(a) : "l"(p));
    return a;
}
#define SWZ128(o) ((o) ^ (((o) >> 3) & 0x70))

__device__ __forceinline__ void cpa16(uint32_t s, const void* g) {
    asm volatile("cp.async.cg.shared.global [%0], [%1], 16;" :: "r"(s), "l"(g));
}
#define CP_COMMIT() asm volatile("cp.async.commit_group;")
#define CP_WAIT1()  asm volatile("cp.async.wait_group 1;" ::: "memory")
#define CP_WAIT0()  asm volatile("cp.async.wait_group 0;" ::: "memory")

__device__ __forceinline__ void ldm_x4(uint32_t* r, uint32_t addr) {
    asm volatile("ldmatrix.sync.aligned.m8n8.x4.shared.b16 {%0,%1,%2,%3}, [%4];"
                 : "=r"(r[0]), "=r"(r[1]), "=r"(r[2]), "=r"(r[3]) : "r"(addr));
}
__device__ __forceinline__ void mma16816(float* c, const uint32_t* a, const uint32_t* b) {
    asm volatile("mma.sync.aligned.m16n8k16.row.col.f32.f16.f16.f32 "
                 "{%0,%1,%2,%3}, {%4,%5,%6,%7}, {%8,%9}, {%0,%1,%2,%3};"
                 : "+f"(c[0]), "+f"(c[1]), "+f"(c[2]), "+f"(c[3])
                 : "r"(a[0]), "r"(a[1]), "r"(a[2]), "r"(a[3]), "r"(b[0]), "r"(b[1]));
}

__device__ __forceinline__ uint32_t pack_h2(float a, float b) {
    __half2 h = __floats2half2_rn(a, b);
    return *reinterpret_cast<uint32_t*>(&h);
}
__device__ __forceinline__ void residual2(uint32_t h, float a, float b, float& ra, float& rb) {
    __half2 hh = *reinterpret_cast<__half2*>(&h);
    ra = a - __low2float(hh);
    rb = b - __high2float(hh);
}

// ----------------------------------------------------------------------------
// mma.sync fp16 2-term GEMM: C = alpha * A @ B^T (+bias) (+causal)
// CTA tile 128x128x64; 256 threads, 8 warps, warp tile 64x32; 2-stage pipe;
// 96KB smem -> 2 CTAs/SM (cross-CTA latency hiding).
// cmode: 0 plain, 1 logits, 2 PV split-K, 3 fused q/k/v projections
// ----------------------------------------------------------------------------
#define OFF_A  0
#define OFF_BH 16384
#define OFF_BL 32768
#define STAGE_B 49152
#define SMEM_GEMM (2 * STAGE_B)

__device__ __forceinline__ void tile_cp(uint32_t sbase, const __half* g,
                                        size_t ldK, int nrows, int tid) {
    const int total = nrows * 8;
    for (int u = tid; u < total; u += 256) {
        int r = u >> 3, c = u & 7;
        uint32_t off = (uint32_t)(r * 128 + c * 16);
        cpa16(sbase + SWZ128(off), (const char*)(g + (size_t)r * ldK) + (c << 4));
    }
}

__global__ __launch_bounds__(256, 2)
void gemm_mma(const __half* __restrict__ Ain, const __half* __restrict__ Bhin,
              const __half* __restrict__ Blin,
              int N, int K, size_t sA, size_t sB, size_t sC,
              float alpha, const float* __restrict__ bias,
              const float* __restrict__ bias2, const float* __restrict__ bias3,
              int cmode,
              float* __restrict__ Cf, __half* __restrict__ Ch,
              __half* __restrict__ Chi, __half* __restrict__ Clo)
{
    const int tid = threadIdx.x;
    const int z = blockIdx.z;
    const int n0 = blockIdx.x * TILE_N;
    int m0, slice = 0;
    if (cmode == 2) {
        const int g = blockIdx.y;
        const int mt = (int)(gridDim.y >> 2) - 1 - (g >> 2);   // heavy first
        slice = g & 3;
        m0 = mt * TILE_M;
    } else {
        m0 = blockIdx.y * TILE_M;
    }
    if (cmode == 1 && n0 > m0) return;          // fully-masked logits tile

    // operand / output selection
    const __half *Ah, *Bh, *Bl;
    const float* bs = bias;
    float* oF = nullptr; __half* oH = nullptr;
    __half *oHi = nullptr, *oLo = nullptr;
    __half *oTh = nullptr, *oTl = nullptr;      // transposed hi/lo (V proj)
    if (cmode == 3) {
        if (z == 0)      { Ah = g_q_hi; Bh = g_WT_hi[0]; Bl = g_WT_lo[0]; bs = bias;  oH = g_qp_h; }
        else if (z == 1) { Ah = g_k_hi; Bh = g_WT_hi[1]; Bl = g_WT_lo[1]; bs = bias2; oHi = g_kp_hi; oLo = g_kp_lo; }
        else             { Ah = g_v_hi; Bh = g_WT_hi[2]; Bl = g_WT_lo[2]; bs = bias3; oTh = g_vpT_hi; oTl = g_vpT_lo; }
    } else {
        Ah = Ain + (size_t)z * sA;
        Bh = Bhin + (size_t)z * sB;
        Bl = Blin + (size_t)z * sB;
        if (Cf)  oF = Cf + ((cmode == 2) ? ((size_t)slice * B_ + z) * sC : (size_t)z * sC);
        if (Ch)  oH = Ch + (size_t)z * sC;
        if (Chi) { oHi = Chi + (size_t)z * sC; oLo = Clo + (size_t)z * sC; }
    }

    // chunk range
    const int NCfull = K / TILE_K;
    int c0 = 0, c1 = NCfull;
    if (cmode == 2) {
        int NCm = (m0 >> 6) + 2;
        if (NCm > NCfull) NCm = NCfull;
        c0 = (slice * NCm) >> 2;
        c1 = ((slice + 1) * NCm) >> 2;
        if (c0 >= c1) {                         // empty slice: zero partial
            const float4 z4 = {0.f, 0.f, 0.f, 0.f};
#pragma unroll
            for (int it = 0; it < 16; it++) {
                int u = tid + (it << 8);
                int r = u >> 5;
                int c4 = (u & 31) << 2;
                *(float4*)(oF + (size_t)(m0 + r) * N + n0 + c4) = z4;
            }
            return;
        }
    }

    extern __shared__ char dsm[];
    const uint32_t sb = smem_u32(dsm);
    const int wid = tid >> 5;
    const int lane = tid & 31;
    const int mrow0 = (wid & 1) * 64;           // 2 warp-rows of 64
    const int ncol0 = (wid >> 1) * 32;          // 4 warp-cols of 32

    const __half* aT = Ah + (size_t)m0 * K;
    const __half* bT = Bh + (size_t)n0 * K;
    const __half* bTl = Bl + (size_t)n0 * K;

    float acc[4][4][4];
#pragma unroll
    for (int i = 0; i < 4; i++)
#pragma unroll
        for (int j = 0; j < 4; j++)
#pragma unroll
            for (int l = 0; l < 4; l++) acc[i][j][l] = 0.f;

    // prologue: prefetch chunk c0
    {
        const size_t ko = (size_t)c0 * TILE_K;
        tile_cp(sb + OFF_A, aT + ko, K, 128, tid);
        tile_cp(sb + OFF_BH, bT + ko, K, 128, tid);
        tile_cp(sb + OFF_BL, bTl + ko, K, 128, tid);
        CP_COMMIT();
    }

    const uint32_t lane15 = (uint32_t)(lane & 15);
    const uint32_t khalf = (uint32_t)((lane >> 4) << 4);

    for (int c = c0; c < c1; c++) {
        if (c + 1 < c1) {
            const uint32_t st = sb + (uint32_t)(((c + 1 - c0) & 1) * STAGE_B);
            const size_t ko = (size_t)(c + 1) * TILE_K;
            tile_cp(st + OFF_A, aT + ko, K, 128, tid);
            tile_cp(st + OFF_BH, bT + ko, K, 128, tid);
            tile_cp(st + OFF_BL, bTl + ko, K, 128, tid);
            CP_COMMIT();
            CP_WAIT1();
        } else {
            CP_WAIT0();
        }
        __syncthreads();

        const uint32_t st = sb + (uint32_t)(((c - c0) & 1) * STAGE_B);
        const uint32_t sA = st + OFF_A, sBh = st + OFF_BH, sBl = st + OFF_BL;

#pragma unroll
        for (int ks = 0; ks < 4; ks++) {
            const uint32_t kb = (uint32_t)(ks * 32) + khalf;
            uint32_t a[4][4];
#pragma unroll
            for (int mt = 0; mt < 4; mt++) {
                const uint32_t ro = (uint32_t)(mrow0 + mt * 16) + lane15;
                ldm_x4(a[mt], sA + SWZ128(ro * 128 + kb));
            }
#pragma unroll
            for (int g = 0; g < 2; g++) {
                const uint32_t ro = (uint32_t)(ncol0 + g * 16) + lane15;
                uint32_t th[4], tl[4];
                ldm_x4(th, sBh + SWZ128(ro * 128 + kb));
                ldm_x4(tl, sBl + SWZ128(ro * 128 + kb));
                uint32_t bh0[2] = {th[0], th[2]}, bh1[2] = {th[1], th[3]};
                uint32_t bl0[2] = {tl[0], tl[2]}, bl1[2] = {tl[1], tl[3]};
#pragma unroll
                for (int mt = 0; mt < 4; mt++) {
                    mma16816(acc[mt][g * 2], a[mt], bh0);
                    mma16816(acc[mt][g * 2], a[mt], bl0);
                    mma16816(acc[mt][g * 2 + 1], a[mt], bh1);
                    mma16816(acc[mt][g * 2 + 1], a[mt], bl1);
                }
            }
        }
        if (c + 1 < c1) __syncthreads();
    }
    __syncthreads();

    // ---- epilogue: regs -> smem stage -> gmem ----
    float* stg = (float*)dsm;
    const int ELD = 132;
    const int rr = lane >> 2;
    const int cc = (lane & 3) * 2;
#pragma unroll
    for (int mt = 0; mt < 4; mt++)
#pragma unroll
        for (int nt = 0; nt < 4; nt++) {
            const int r = mrow0 + mt * 16 + rr;
            const int cn = ncol0 + nt * 8 + cc;
            stg[r * ELD + cn]           = acc[mt][nt][0];
            stg[r * ELD + cn + 1]       = acc[mt][nt][1];
            stg[(r + 8) * ELD + cn]     = acc[mt][nt][2];
            stg[(r + 8) * ELD + cn + 1] = acc[mt][nt][3];
        }
    __syncthreads();

    if (oTh) {
        // transposed hi/lo write: vpT[b][n][s], tile (m0, n0)
        const int b = m0 >> 12;
        const int s0 = m0 & (S_ - 1);
#pragma unroll 1
        for (int it = 0; it < 16; it++) {
            const int u = tid + (it << 8);       // 0..4095
            const int nl = u >> 5;               // local col 0..127
            const int mq = (u & 31) << 2;        // 0..124
            const int n = n0 + nl;
            const float bv = bs[n];
            float v0 = stg[(mq + 0) * ELD + nl] + bv;
            float v1 = stg[(mq + 1) * ELD + nl] + bv;
            float v2 = stg[(mq + 2) * ELD + nl] + bv;
            float v3 = stg[(mq + 3) * ELD + nl] + bv;
            uint32_t h0 = pack_h2(v0, v1), h1 = pack_h2(v2, v3);
            float r0, r1, r2, r3;
            residual2(h0, v0, v1, r0, r1);
            residual2(h1, v2, v3, r2, r3);
            const size_t o = ((size_t)b * D_ + n) * S_ + s0 + mq;
            uint2 hv = {h0, h1};
            uint2 lv = {pack_h2(r0, r1), pack_h2(r2, r3)};
            *(uint2*)(oTh + o) = hv;
            *(uint2*)(oTl + o) = lv;
        }
        return;
    }

#pragma unroll 1
    for (int it = 0; it < 16; it++) {
        const int u = tid + (it << 8);
        const int r = u >> 5;
        const int f = (u & 31) << 2;
        const float* s = stg + r * ELD + f;
        float v0 = s[0] * alpha, v1 = s[1] * alpha, v2 = s[2] * alpha, v3 = s[3] * alpha;
        const int n = n0 + f;
        const int mi = m0 + r;
        const size_t m = (size_t)mi;
        if (bs) {
            float4 bv = *(const float4*)(bs + n);
            v0 += bv.x; v1 += bv.y; v2 += bv.z; v3 += bv.w;
        }
        if (cmode == 1) {
            if (n + 0 > mi) v0 += -1e9f;
            if (n + 1 > mi) v1 += -1e9f;
            if (n + 2 > mi) v2 += -1e9f;
            if (n + 3 > mi) v3 += -1e9f;
        }
        const size_t o = m * (size_t)N + n;
        if (oF) {
            float4 ov = {v0, v1, v2, v3};
            *(float4*)(oF + o) = ov;
        }
        if (oH) {
            uint2 hv = {pack_h2(v0, v1), pack_h2(v2, v3)};
            *(uint2*)(oH + o) = hv;
        }
        if (oHi) {
            uint32_t h0 = pack_h2(v0, v1), h1 = pack_h2(v2, v3);
            float r0, r1, r2, r3;
            residual2(h0, v0, v1, r0, r1);
            residual2(h1, v2, v3, r2, r3);
            uint2 hv = {h0, h1};
            uint2 lv = {pack_h2(r0, r1), pack_h2(r2, r3)};
            *(uint2*)(oHi + o) = hv;
            *(uint2*)(oLo + o) = lv;
        }
    }
}

// ---------------- fused input -> fp16 hi (z picks q/k/v) ----------------
__global__ __launch_bounds__(256)
void convert_hi3(const float* __restrict__ q, const float* __restrict__ k,
                 const float* __restrict__ v, int n4)
{
    int i = blockIdx.x * blockDim.x + threadIdx.x;
    if (i >= n4) return;
    const float* in;
    __half* hi;
    if (blockIdx.z == 0)      { in = q; hi = g_q_hi; }
    else if (blockIdx.z == 1) { in = k; hi = g_k_hi; }
    else                      { in = v; hi = g_v_hi; }
    float4 vv = ((const float4*)in)[i];
    uint2 hv = {pack_h2(vv.x, vv.y), pack_h2(vv.z, vv.w)};
    ((uint2*)hi)[i] = hv;
}

// ---------------- fused weight transpose+split (z picks Wq/Wk/Wv/Wo) ----------------
__global__ __launch_bounds__(256)
void transpose_W(const float* __restrict__ Wq, const float* __restrict__ Wk,
                 const float* __restrict__ Wv, const float* __restrict__ Wo)
{
    __shared__ float t[32][33];
    const int z = blockIdx.z;
    const float* in = (z == 0) ? Wq : (z == 1) ? Wk : (z == 2) ? Wv : Wo;
    __half* ohi = &g_WT_hi[z][0];
    __half* olo = &g_WT_lo[z][0];
    const int r0 = blockIdx.y * 32, c0 = blockIdx.x * 32;
    const int tx = threadIdx.x, ty = threadIdx.y;
#pragma unroll
    for (int j = 0; j < 32; j += 8)
        t[ty + j][tx] = in[(size_t)(r0 + ty + j) * D_ + c0 + tx];
    __syncthreads();
#pragma unroll
    for (int j = 0; j < 32; j += 8) {
        float v = t[tx][ty + j];
        __half h = __float2half_rn(v);
        __half l = __float2half_rn(v - __half2float(h));
        size_t o = (size_t)(c0 + ty + j) * D_ + r0 + tx;
        ohi[o] = h; olo[o] = l;
    }
}

// ---------------- PV split-K reduce: ctx hi = sum of 4 partials ----------------
__global__ __launch_bounds__(256)
void reduce_ctx(int n4)
{
    int i = blockIdx.x * blockDim.x + threadIdx.x;
    if (i >= n4) return;
    const size_t stride = (size_t)BS_ * D_ / 4;
    const float4* p = (const float4*)&g_pv_part[0][0];
    float4 a = p[i], b = p[i + stride], c = p[i + 2 * stride], d = p[i + 3 * stride];
    float v0 = a.x + b.x + c.x + d.x;
    float v1 = a.y + b.y + c.y + d.y;
    float v2 = a.z + b.z + c.z + d.z;
    float v3 = a.w + b.w + c.w + d.w;
    uint2 hv = {pack_h2(v0, v1), pack_h2(v2, v3)};
    ((uint2*)g_ctx_hi)[i] = hv;
}

// ---------------- causal softmax: 256 threads ----------------
__global__ __launch_bounds__(256)
void softmax_kernel(float* __restrict__ attn, __half* __restrict__ ah)
{
    __shared__ float buf[S_];
    __shared__ float red[8];
    __shared__ float s_max, s_sum;

    const size_t rb = (size_t)blockIdx.x * S_;
    float* row = attn + rb;
    const int t = threadIdx.x;
    const int m = blockIdx.x & (S_ - 1);
    const int L = m + 1;
    const int L4 = (L + 3) & ~3;
    const int Lpad = ((m >> 7) + 1) << 7;
    const float NINF = __int_as_float(0xff800000);

    float mx = -1e30f;
    for (int i = t * 4; i < L4; i += 1024) {
        float4 v = *(const float4*)(row + i);
        if (i + 0 >= L) v.x = NINF;
        if (i + 1 >= L) v.y = NINF;
        if (i + 2 >= L) v.z = NINF;
        if (i + 3 >= L) v.w = NINF;
        *(float4*)(buf + i) = v;
        mx = fmaxf(mx, fmaxf(fmaxf(v.x, v.y), fmaxf(v.z, v.w)));
    }
#pragma unroll
    for (int o = 16; o; o >>= 1) mx = fmaxf(mx, __shfl_xor_sync(0xffffffffu, mx, o));
    if ((t & 31) == 0) red[t >> 5] = mx;
    __syncthreads();
    if (t == 0) {
        float v = red[0];
#pragma unroll
        for (int i = 1; i < 8; i++) v = fmaxf(v, red[i]);
        s_max = v;
    }
    __syncthreads();
    const float mxv = s_max;

    float sum = 0.f;
    for (int i = t * 4; i < L4; i += 1024) {
        float4 v = *(const float4*)(buf + i);
        v.x = __expf(v.x - mxv); v.y = __expf(v.y - mxv);
        v.z = __expf(v.z - mxv); v.w = __expf(v.w - mxv);
        *(float4*)(buf + i) = v;
        sum += v.x + v.y + v.z + v.w;
    }
#pragma unroll
    for (int o = 16; o; o >>= 1) sum += __shfl_xor_sync(0xffffffffu, sum, o);
    if ((t & 31) == 0) red[t >> 5] = sum;
    __syncthreads();
    if (t == 0) {
        float v = red[0];
#pragma unroll
        for (int i = 1; i < 8; i++) v += red[i];
        s_sum = v;
    }
    __syncthreads();
    const float inv = 1.f / s_sum;

    for (int i = t * 4; i < L4; i += 1024) {
        float4 v = *(const float4*)(buf + i);
        v.x *= inv; v.y *= inv; v.z *= inv; v.w *= inv;
        *(float4*)(row + i) = v;
        uint2 hv = {pack_h2(v.x, v.y), pack_h2(v.z, v.w)};
        *(uint2*)(ah + rb + i) = hv;
    }
    const uint2 z2 = {0u, 0u};
    const float4 z4 = {0.f, 0.f, 0.f, 0.f};
    for (int i = L4 + t * 4; i < S_; i += 1024) {
        *(float4*)(row + i) = z4;
        if (i < Lpad) *(uint2*)(ah + rb + i) = z2;
    }
}

// ---------------- launch ----------------
extern "C" void kernel_launch(void* const* d_in, const int* in_sizes, int n_in,
                              void* d_out, int out_size)
{
    const float* q    = (const float*)d_in[0];
    const float* k    = (const float*)d_in[1];
    const float* v    = (const float*)d_in[2];
    const float* Wq   = (const float*)d_in[4];
    const float* bq   = (const float*)d_in[5];
    const float* Wk   = (const float*)d_in[6];
    const float* bk   = (const float*)d_in[7];
    const float* Wv   = (const float*)d_in[8];
    const float* bv   = (const float*)d_in[9];
    const float* Wo   = (const float*)d_in[10];
    const float* bo   = (const float*)d_in[11];

#define SYM(p, s) cudaGetSymbolAddress((void**)&p, s)
    __half *qph, *kph, *kpl, *vpTh, *vpTl, *ctxh, *ath;
    __half *WTh, *WTl;
    float *pvp, *attn_scr, *z_scr;
    SYM(qph, g_qp_h);
    SYM(kph, g_kp_hi); SYM(kpl, g_kp_lo);
    SYM(vpTh, g_vpT_hi); SYM(vpTl, g_vpT_lo);
    SYM(ctxh, g_ctx_hi);
    SYM(ath, g_attn_h);
    SYM(WTh, (g_WT_hi[0][0]));   SYM(WTl, (g_WT_lo[0][0]));
    SYM(pvp, (g_pv_part[0][0]));
    SYM(attn_scr, g_attn_f); SYM(z_scr, g_z);

    const size_t zN = (size_t)BS_ * D_;
    const size_t aN = (size_t)B_ * S_ * S_;
    float* out = (float*)d_out;
    float *z_out, *attn_out;
    if ((size_t)out_size >= zN + aN) { z_out = out; attn_out = out + zN; }
    else if ((size_t)out_size == aN) { attn_out = out; z_out = z_scr; }
    else                             { z_out = out; attn_out = attn_scr; }

    cudaFuncSetAttribute(gemm_mma, cudaFuncAttributeMaxDynamicSharedMemorySize, SMEM_GEMM);

    const int n4 = BS_ * D_ / 4;
    dim3 tb(32, 8);

    // 0) inputs -> fp16 hi (fused q,k,v)
    dim3 gcv((n4 + 255) / 256, 1, 3);
    convert_hi3<<<gcv, 256>>>(q, k, v, n4);

    // 1) transpose+split all weights
    dim3 tgw(D_ / 32, D_ / 32, 4);
    transpose_W<<<tgw, tb>>>(Wq, Wk, Wv, Wo);

    // 2) fused projections (cmode 3); V writes vpT hi/lo transposed
    dim3 gproj3(D_ / TILE_N, BS_ / TILE_M, 3);
    gemm_mma<<<gproj3, 256, SMEM_GEMM>>>(nullptr, nullptr, nullptr,
        D_, D_, 0, 0, 0, 1.f, bq, bk, bv, 3, nullptr, nullptr, nullptr, nullptr);

    // 3) logits = qp @ kp^T / 16 + causal (cmode 1)
    dim3 glog(S_ / TILE_N, S_ / TILE_M, B_);
    gemm_mma<<<glog, 256, SMEM_GEMM>>>(qph, kph, kpl,
        S_, D_, (size_t)S_ * D_, (size_t)S_ * D_, (size_t)S_ * S_,
        1.f / 16.f, nullptr, nullptr, nullptr, 1, attn_out, nullptr, nullptr, nullptr);

    // 4) causal softmax (+ fp16 emit)
    softmax_kernel<<<B_ * S_, 256>>>(attn_out, ath);

    // 5) PV split-K (cmode 2; fp32 partials)
    dim3 gpv(D_ / TILE_N, (S_ / TILE_M) * 4, B_);
    gemm_mma<<<gpv, 256, SMEM_GEMM>>>(ath, vpTh, vpTl,
        D_, S_, (size_t)S_ * S_, (size_t)D_ * S_, (size_t)S_ * D_,
        1.f, nullptr, nullptr, nullptr, 2, pvp, nullptr, nullptr, nullptr);

    // 6) reduce partials -> ctx hi
    reduce_ctx<<<(n4 + 255) / 256, 256>>>(n4);

    // 7) z = ctx @ Wo + bo (cmode 0)
    gemm_mma<<<dim3(D_ / TILE_N, BS_ / TILE_M, 1), 256, SMEM_GEMM>>>(ctxh,
        WTh + 3 * D_ * D_, WTl + 3 * D_ * D_,
        D_, D_, 0, 0, 0, 1.f, bo, nullptr, nullptr, 0, z_out, nullptr, nullptr, nullptr);
}